// round 1
// baseline (speedup 1.0000x reference)
#include <cuda_runtime.h>

typedef unsigned long long ull;

#define SEQ   512
#define HD    64
#define G4    256          // 4*H
#define ROWS  16           // batch rows per CTA
#define NCTA  128          // 2048 / 16
#define NTHR  256
#define OUTF  72
#define XP    18           // Xdup pitch in ull (bank-conflict break)

// SMEM: W0s[64][256] f32 | W1s[128][256] f32 | gates[16][256] f32 | Xdup[128][XP] u64
#define SMEM_BYTES (((64*256) + (128*256) + (16*256))*4 + 128*XP*8)   // 231424

__device__ __forceinline__ ull pack2(float a, float b) {
    ull r; asm("mov.b64 %0, {%1, %2};" : "=l"(r) : "f"(a), "f"(b)); return r;
}
__device__ __forceinline__ void fma2(ull &d, ull a, ull b) {
    // packed fp32x2 FMA (sm_100+): d = a*b + d, elementwise on the two f32 lanes
    asm("fma.rn.f32x2 %0, %1, %2, %0;" : "+l"(d) : "l"(a), "l"(b));
}
__device__ __forceinline__ float sigf(float x) {
    // safe for any x: exp(-x) may be inf -> 1/inf = 0 (correct limit)
    return __fdividef(1.0f, 1.0f + __expf(-x));
}
__device__ __forceinline__ float tanhf_(float x) {
    // overflow-safe: exp(-2|x|) in (0,1]
    float e = __expf(-2.0f * fabsf(x));
    float r = __fdividef(1.0f - e, 1.0f + e);
    return copysignf(r, x);
}

__device__ __forceinline__ void lstm_state(const float* __restrict__ gsh,
                                           ull* __restrict__ Xd,
                                           int sk, int sr0, float* c, int koff)
{
    ull hv[4];
    #pragma unroll
    for (int i = 0; i < 4; ++i) {
        int base = (sr0 + i) * G4 + sk;
        float ii = sigf  (gsh[base]);
        float ff = sigf  (gsh[base + 64]);
        float g_ = tanhf_(gsh[base + 128]);
        float oo = sigf  (gsh[base + 192]);
        float cc = ff * c[i] + ii * g_;
        c[i] = cc;
        float hh = oo * tanhf_(cc);
        hv[i] = pack2(hh, hh);
    }
    *(ulonglong2*)&Xd[(koff + sk) * XP + sr0]     = make_ulonglong2(hv[0], hv[1]);
    *(ulonglong2*)&Xd[(koff + sk) * XP + sr0 + 2] = make_ulonglong2(hv[2], hv[3]);
}

__global__ __launch_bounds__(NTHR, 1)
void lstm_forecaster_kernel(const float* __restrict__ x,
                            const float* __restrict__ Wih0,
                            const float* __restrict__ Whh0,
                            const float* __restrict__ bih0,
                            const float* __restrict__ bhh0,
                            const float* __restrict__ Wih1,
                            const float* __restrict__ Whh1,
                            const float* __restrict__ bih1,
                            const float* __restrict__ bhh1,
                            const float* __restrict__ fcw,
                            const float* __restrict__ fcb,
                            float* __restrict__ out)
{
    extern __shared__ float sm[];
    float* W0s = sm;                         // [64][256]  k-major (transposed)
    float* W1s = sm + 64 * G4;               // [128][256] k-major: k<64 = Wih1, k>=64 = Whh1
    float* gsh = sm + (64 + 128) * G4;       // [16][256]  gate scratch
    ull*   Xd  = (ull*)(sm + (64 + 128 + 16) * G4);  // [128][XP]: k<64 h0 dup, k>=64 h1 dup

    const int tid  = threadIdx.x;
    const int warp = tid >> 5, lane = tid & 31;
    const int rr   = lane >> 3, gg = lane & 7;
    const int cb   = warp * 32 + gg * 4;     // 4 gate cols for this thread
    const int gr0  = rr << 2;                // 4 GEMM rows for this thread
    const int sk   = tid & 63;               // state k index
    const int sr0  = (tid >> 6) << 2;        // 4 state rows for this thread

    // ---- load transposed weights into shared (one-time) ----
    for (int idx = tid; idx < 64 * G4; idx += NTHR) {
        int k = idx >> 8, g = idx & 255;
        W0s[idx] = Whh0[g * HD + k];
    }
    for (int idx = tid; idx < 128 * G4; idx += NTHR) {
        int k = idx >> 8, g = idx & 255;
        W1s[idx] = (k < 64) ? Wih1[g * HD + k] : Whh1[g * HD + (k - 64)];
    }
    for (int idx = tid; idx < 128 * XP; idx += NTHR) Xd[idx] = 0ull;

    // ---- per-thread constant registers (packed pairs) ----
    ull w0p0 = pack2(Wih0[cb + 0], Wih0[cb + 1]);
    ull w0p1 = pack2(Wih0[cb + 2], Wih0[cb + 3]);
    ull b0p0 = pack2(bih0[cb + 0] + bhh0[cb + 0], bih0[cb + 1] + bhh0[cb + 1]);
    ull b0p1 = pack2(bih0[cb + 2] + bhh0[cb + 2], bih0[cb + 3] + bhh0[cb + 3]);
    ull b1p0 = pack2(bih1[cb + 0] + bhh1[cb + 0], bih1[cb + 1] + bhh1[cb + 1]);
    ull b1p1 = pack2(bih1[cb + 2] + bhh1[cb + 2], bih1[cb + 3] + bhh1[cb + 3]);

    float c0[4] = {0.f, 0.f, 0.f, 0.f};
    float c1[4] = {0.f, 0.f, 0.f, 0.f};

    const int gRow = blockIdx.x * ROWS;

    float xr0 = x[(gRow + gr0 + 0) * SEQ];
    float xr1 = x[(gRow + gr0 + 1) * SEQ];
    float xr2 = x[(gRow + gr0 + 2) * SEQ];
    float xr3 = x[(gRow + gr0 + 3) * SEQ];

    __syncthreads();

    for (int s = 0; s < SEQ; ++s) {
        // ================= layer 0 GEMM: gates = x*w0 + b0 + h0 @ Whh0^T ==========
        ull a00 = b0p0, a01 = b0p1, a10 = b0p0, a11 = b0p1;
        ull a20 = b0p0, a21 = b0p1, a30 = b0p0, a31 = b0p1;
        {
            ull xx0 = pack2(xr0, xr0), xx1 = pack2(xr1, xr1);
            ull xx2 = pack2(xr2, xr2), xx3 = pack2(xr3, xr3);
            fma2(a00, xx0, w0p0); fma2(a01, xx0, w0p1);
            fma2(a10, xx1, w0p0); fma2(a11, xx1, w0p1);
            fma2(a20, xx2, w0p0); fma2(a21, xx2, w0p1);
            fma2(a30, xx3, w0p0); fma2(a31, xx3, w0p1);
        }
        // prefetch next timestep's x (hidden under the GEMM)
        int sn = (s + 1 < SEQ) ? (s + 1) : s;
        float xn0 = x[(gRow + gr0 + 0) * SEQ + sn];
        float xn1 = x[(gRow + gr0 + 1) * SEQ + sn];
        float xn2 = x[(gRow + gr0 + 2) * SEQ + sn];
        float xn3 = x[(gRow + gr0 + 3) * SEQ + sn];

        #pragma unroll 8
        for (int k = 0; k < HD; ++k) {
            ulonglong2 hA = *(const ulonglong2*)&Xd[k * XP + gr0];
            ulonglong2 hB = *(const ulonglong2*)&Xd[k * XP + gr0 + 2];
            ulonglong2 wv = *(const ulonglong2*)&W0s[k * G4 + cb];
            fma2(a00, hA.x, wv.x); fma2(a01, hA.x, wv.y);
            fma2(a10, hA.y, wv.x); fma2(a11, hA.y, wv.y);
            fma2(a20, hB.x, wv.x); fma2(a21, hB.x, wv.y);
            fma2(a30, hB.y, wv.x); fma2(a31, hB.y, wv.y);
        }
        xr0 = xn0; xr1 = xn1; xr2 = xn2; xr3 = xn3;

        *(ulonglong2*)&gsh[(gr0 + 0) * G4 + cb] = make_ulonglong2(a00, a01);
        *(ulonglong2*)&gsh[(gr0 + 1) * G4 + cb] = make_ulonglong2(a10, a11);
        *(ulonglong2*)&gsh[(gr0 + 2) * G4 + cb] = make_ulonglong2(a20, a21);
        *(ulonglong2*)&gsh[(gr0 + 3) * G4 + cb] = make_ulonglong2(a30, a31);
        __syncthreads();

        // ================= layer 0 state update -> h0 into Xd[0:64] ===============
        lstm_state(gsh, Xd, sk, sr0, c0, 0);
        __syncthreads();

        // ================= layer 1 GEMM: gates = b1 + [h0,h1] @ [Wih1;Whh1]^T =====
        a00 = b1p0; a01 = b1p1; a10 = b1p0; a11 = b1p1;
        a20 = b1p0; a21 = b1p1; a30 = b1p0; a31 = b1p1;
        #pragma unroll 8
        for (int k = 0; k < 2 * HD; ++k) {
            ulonglong2 hA = *(const ulonglong2*)&Xd[k * XP + gr0];
            ulonglong2 hB = *(const ulonglong2*)&Xd[k * XP + gr0 + 2];
            ulonglong2 wv = *(const ulonglong2*)&W1s[k * G4 + cb];
            fma2(a00, hA.x, wv.x); fma2(a01, hA.x, wv.y);
            fma2(a10, hA.y, wv.x); fma2(a11, hA.y, wv.y);
            fma2(a20, hB.x, wv.x); fma2(a21, hB.x, wv.y);
            fma2(a30, hB.y, wv.x); fma2(a31, hB.y, wv.y);
        }
        *(ulonglong2*)&gsh[(gr0 + 0) * G4 + cb] = make_ulonglong2(a00, a01);
        *(ulonglong2*)&gsh[(gr0 + 1) * G4 + cb] = make_ulonglong2(a10, a11);
        *(ulonglong2*)&gsh[(gr0 + 2) * G4 + cb] = make_ulonglong2(a20, a21);
        *(ulonglong2*)&gsh[(gr0 + 3) * G4 + cb] = make_ulonglong2(a30, a31);
        __syncthreads();

        // ================= layer 1 state update -> h1 into Xd[64:128] =============
        lstm_state(gsh, Xd, sk, sr0, c1, 64);
        __syncthreads();
    }

    // ================= final FC: out = h1_last @ fcw^T + fcb ======================
    const float* XdF = (const float*)Xd;
    for (int idx = tid; idx < ROWS * OUTF; idx += NTHR) {
        int r = idx / OUTF;
        int o = idx - r * OUTF;
        float acc = fcb[o];
        #pragma unroll 16
        for (int k = 0; k < HD; ++k) {
            float h = XdF[((64 + k) * XP + r) * 2];   // low half of dup pair
            acc = fmaf(h, fcw[o * HD + k], acc);
        }
        out[(gRow + r) * OUTF + o] = acc;
    }
}

extern "C" void kernel_launch(void* const* d_in, const int* in_sizes, int n_in,
                              void* d_out, int out_size)
{
    (void)in_sizes; (void)n_in; (void)out_size;
    cudaFuncSetAttribute(lstm_forecaster_kernel,
                         cudaFuncAttributeMaxDynamicSharedMemorySize, SMEM_BYTES);
    lstm_forecaster_kernel<<<NCTA, NTHR, SMEM_BYTES>>>(
        (const float*)d_in[0],   // x
        (const float*)d_in[1],   // W_ih_l0
        (const float*)d_in[2],   // W_hh_l0
        (const float*)d_in[3],   // b_ih_l0
        (const float*)d_in[4],   // b_hh_l0
        (const float*)d_in[5],   // W_ih_l1
        (const float*)d_in[6],   // W_hh_l1
        (const float*)d_in[7],   // b_ih_l1
        (const float*)d_in[8],   // b_hh_l1
        (const float*)d_in[9],   // fc_w
        (const float*)d_in[10],  // fc_b
        (float*)d_out);
}